// round 11
// baseline (speedup 1.0000x reference)
#include <cuda_runtime.h>

// SKA forward: out[b, g*16+cg, h, w] = sum_{k} x_pad[b, g*16+cg, h+di, w+dj] * w[b, cg, k, h, w]
// x (16,512,56,56) f32, w (16,16,9,56,56) f32, out (16,512,56,56) f32.
// R11: R10 + register double-buffered software pipeline over group-pairs:
//   iter p: prefetch.L2 pair p+2  ->  demand-load pair p+1 into buffer B
//           -> compute/store pair p from buffer A.
// Every warp keeps a 6x512B load batch outstanding continuously (~100% duty)
// instead of ~20%, breaking the 4 TB/s in-flight-bytes plateau.

#define NB   16
#define NC   512
#define NG   32
#define NCG  16
#define NH   56
#define NW   56
#define NW4  14            // 56 / 4
#define PLANE   (NH * NW)  // 3136
#define GSPLIT  4
#define GPT     (NG / GSPLIT)   // 8 groups per thread -> 4 pairs
#define CSTRIDE (NCG * PLANE)   // stride between consecutive groups (same cg)

__device__ __forceinline__ void pf_l2(const float* p) {
    asm volatile("prefetch.global.L2 [%0];" :: "l"(p));
}

__global__ __launch_bounds__(128, 4) void ska_kernel(
    const float* __restrict__ x,
    const float* __restrict__ wt,
    float* __restrict__ out)
{
    const int idx = blockIdx.x * 128 + threadIdx.x;
    const int lane = threadIdx.x & 31;
    // idx = (((b*GSPLIT + gs)*NCG + cg)*NH + h)*NW4 + w4
    const int w4 = idx % NW4;
    int t        = idx / NW4;
    const int h  = t % NH;  t /= NH;
    const int cg = t % NCG; t /= NCG;
    const int gs = t % GSPLIT;
    const int b  = t / GSPLIT;
    const int col = w4 * 4;

    const bool hm = (h > 0);
    const bool hp = (h < NH - 1);
    const bool wl = (col > 0);
    const bool wr = (col < NW - 4);

    const float* wb = wt + ((((b * NCG + cg) * 9) * NH + h) * NW + col);
    const int base  = (b * NC + (gs * GPT) * NCG + cg) * PLANE + h * NW + col;
    const float* xb = x + base;
    float* ob       = out + base;

    // ---- prefetch pair 1 (groups 2,3) before anything blocks ----
#pragma unroll
    for (int j = 2; j < 4; ++j)
#pragma unroll
        for (int di = 0; di < 3; ++di) {
            const bool v = (di == 1) || (di == 0 && hm) || (di == 2 && hp);
            if (v) pf_l2(xb + j * CSTRIDE + (di - 1) * NW);
        }

    // ---- 9 weight float4s (reused across 8 groups) ----
    float4 wk[9];
#pragma unroll
    for (int k = 0; k < 9; ++k)
        wk[k] = *reinterpret_cast<const float4*>(wb + k * PLANE);

    // ---- double buffer: xm[buf][group-in-pair][row] ----
    float4 xm[2][2][3];

    // demand-load pair 0 into buffer 0
#pragma unroll
    for (int jj = 0; jj < 2; ++jj)
#pragma unroll
        for (int di = 0; di < 3; ++di) {
            const bool v = (di == 1) || (di == 0 && hm) || (di == 2 && hp);
            xm[0][jj][di] = make_float4(0.f, 0.f, 0.f, 0.f);
            if (v) xm[0][jj][di] = *reinterpret_cast<const float4*>(
                                       xb + jj * CSTRIDE + (di - 1) * NW);
        }

#pragma unroll
    for (int p = 0; p < 4; ++p) {          // pair p = groups 2p, 2p+1
        const int cur = p & 1;
        const int nxt = cur ^ 1;

        // ---- prefetch pair p+2 (groups 2p+4, 2p+5) ----
        if (p + 2 < 4) {
#pragma unroll
            for (int jj = 0; jj < 2; ++jj)
#pragma unroll
                for (int di = 0; di < 3; ++di) {
                    const bool v = (di == 1) || (di == 0 && hm) || (di == 2 && hp);
                    if (v) pf_l2(xb + (2 * p + 4 + jj) * CSTRIDE + (di - 1) * NW);
                }
        }

        // ---- demand-load pair p+1 into the other buffer ----
        if (p + 1 < 4) {
#pragma unroll
            for (int jj = 0; jj < 2; ++jj)
#pragma unroll
                for (int di = 0; di < 3; ++di) {
                    const bool v = (di == 1) || (di == 0 && hm) || (di == 2 && hp);
                    xm[nxt][jj][di] = make_float4(0.f, 0.f, 0.f, 0.f);
                    if (v) xm[nxt][jj][di] = *reinterpret_cast<const float4*>(
                                                 xb + (2 * p + 2 + jj) * CSTRIDE + (di - 1) * NW);
                }
        }

        // ---- compute pair p from current buffer ----
#pragma unroll
        for (int jj = 0; jj < 2; ++jj) {
            const int g = 2 * p + jj;

            float xl[3], xr[3];
#pragma unroll
            for (int di = 0; di < 3; ++di) {
                xl[di] = __shfl_up_sync(0xffffffffu,  xm[cur][jj][di].w, 1);
                xr[di] = __shfl_down_sync(0xffffffffu, xm[cur][jj][di].x, 1);
            }
#pragma unroll
            for (int di = 0; di < 3; ++di) {
                const bool v = (di == 1) || (di == 0 && hm) || (di == 2 && hp);
                if (lane == 0  && wl) xl[di] = v ? xb[g * CSTRIDE + (di - 1) * NW - 1] : 0.f;
                if (lane == 31 && wr) xr[di] = v ? xb[g * CSTRIDE + (di - 1) * NW + 4] : 0.f;
                if (!wl) xl[di] = 0.f;   // image edges: halo is zero
                if (!wr) xr[di] = 0.f;
            }

            float4 a = make_float4(0.f, 0.f, 0.f, 0.f);
#pragma unroll
            for (int di = 0; di < 3; ++di) {
                const float4 w0 = wk[di * 3 + 0];
                const float4 w1 = wk[di * 3 + 1];
                const float4 w2 = wk[di * 3 + 2];
                const float4 m  = xm[cur][jj][di];

                a.x = fmaf(xl[di], w0.x, a.x);
                a.y = fmaf(m.x,    w0.y, a.y);
                a.z = fmaf(m.y,    w0.z, a.z);
                a.w = fmaf(m.z,    w0.w, a.w);

                a.x = fmaf(m.x,    w1.x, a.x);
                a.y = fmaf(m.y,    w1.y, a.y);
                a.z = fmaf(m.z,    w1.z, a.z);
                a.w = fmaf(m.w,    w1.w, a.w);

                a.x = fmaf(m.y,    w2.x, a.x);
                a.y = fmaf(m.z,    w2.y, a.y);
                a.z = fmaf(m.w,    w2.z, a.z);
                a.w = fmaf(xr[di], w2.w, a.w);
            }
            __stcs(reinterpret_cast<float4*>(ob + g * CSTRIDE), a);
        }
    }
}

extern "C" void kernel_launch(void* const* d_in, const int* in_sizes, int n_in,
                              void* d_out, int out_size)
{
    const float* x  = (const float*)d_in[0];
    const float* wt = (const float*)d_in[1];
    float* out      = (float*)d_out;

    const int total  = NB * GSPLIT * NCG * NH * NW4; // 802816 threads
    const int blocks = total / 128;                  // 6272
    ska_kernel<<<blocks, 128>>>(x, wt, out);
}